// round 9
// baseline (speedup 1.0000x reference)
#include <cuda_runtime.h>
#include <cstdint>

#define NN        8192
#define KSEL      64
#define NTHREADS  256
#define NBLK      456            // 152 SMs x 3 blocks (persistent)
#define WCAP      64             // per-warp candidate slots
#define FCAP      (8 * WCAP)     // 512
#define DCAP      256
#define THRESH    2.25f

#define ROWB      (NN * 4)       // 32768 bytes per row buffer
#define OFF_BUF0  0
#define OFF_BUF1  32768
#define OFF_ZBUF  65536          // 4096
#define OFF_SEG   69632          // 4096 (512 x u64)
#define OFF_DH    73728          // 2048: dcand (fast) / hist (fallback) union
#define OFF_CNT   75776          // 32: cnt_s[8]
#define OFF_WSUM  75808          // 32
#define OFF_CTR   75840          // 16: fb_count, sh_b, sh_kp, sh_deg
#define OFF_MBAR  75856          // 16: two mbarriers
#define SMEM_TOTAL 75872

__device__ __forceinline__ uint64_t make_key(uint32_t bits, uint32_t idx) {
    return ((uint64_t)bits << 16) | (uint64_t)(0xFFFFu ^ idx);
}

__device__ __forceinline__ uint32_t smem_u32(const void* p) {
    return (uint32_t)__cvta_generic_to_shared(p);
}

__device__ __forceinline__ void mbar_init(uint32_t mbar, uint32_t cnt) {
    asm volatile("mbarrier.init.shared.b64 [%0], %1;" :: "r"(mbar), "r"(cnt) : "memory");
}
__device__ __forceinline__ void mbar_expect_tx(uint32_t mbar, uint32_t bytes) {
    asm volatile("mbarrier.arrive.expect_tx.shared.b64 _, [%0], %1;" :: "r"(mbar), "r"(bytes) : "memory");
}
__device__ __forceinline__ void mbar_wait(uint32_t mbar, uint32_t phase) {
    asm volatile(
        "{\n\t.reg .pred P;\n\t"
        "W%=:\n\t"
        "mbarrier.try_wait.parity.acquire.cta.shared::cta.b64 P, [%0], %1, 0x989680;\n\t"
        "@P bra D%=;\n\t"
        "bra W%=;\n\t"
        "D%=:\n\t}"
        :: "r"(mbar), "r"(phase) : "memory");
}
__device__ __forceinline__ void bulk_g2s(uint32_t dst, const void* src, uint32_t bytes, uint32_t mbar) {
    asm volatile("cp.async.bulk.shared::cluster.global.mbarrier::complete_tx::bytes [%0], [%1], %2, [%3];"
                 :: "r"(dst), "l"(src), "r"(bytes), "r"(mbar) : "memory");
}
__device__ __forceinline__ void bulk_s2g(void* dst, uint32_t src, uint32_t bytes) {
    asm volatile("cp.async.bulk.global.shared::cta.bulk_group [%0], [%1], %2;"
                 :: "l"(dst), "r"(src), "r"(bytes) : "memory");
}

// Warp-aggregated histogram add (fallback only).
__device__ __forceinline__ void hist_add(uint32_t* hist, uint32_t bin, bool pred, int lane) {
    unsigned act = __ballot_sync(0xffffffffu, pred);
    if (pred) {
        unsigned same   = __match_any_sync(act, bin);
        int      leader = __ffs(same) - 1;
        if (lane == leader) atomicAdd(&hist[bin], (uint32_t)__popc(same));
    }
}

extern __shared__ char smem[];

__global__ __launch_bounds__(NTHREADS)
void topk_mask_kernel(const float* __restrict__ A, float* __restrict__ out)
{
    const int tid  = threadIdx.x;
    const int lane = tid & 31;
    const int warp = tid >> 5;
    const unsigned ltm = (1u << lane) - 1u;

    float4*   zbuf  = reinterpret_cast<float4*>(smem + OFF_ZBUF);
    uint64_t* seg   = reinterpret_cast<uint64_t*>(smem + OFF_SEG);
    uint64_t* dcand = reinterpret_cast<uint64_t*>(smem + OFF_DH);
    uint32_t* hist  = reinterpret_cast<uint32_t*>(smem + OFF_DH);
    uint32_t* cnt_s = reinterpret_cast<uint32_t*>(smem + OFF_CNT);
    uint32_t* wsum  = reinterpret_cast<uint32_t*>(smem + OFF_WSUM);
    uint32_t* ctr   = reinterpret_cast<uint32_t*>(smem + OFF_CTR);  // fb,b,kp,deg
    const uint32_t mb0 = smem_u32(smem + OFF_MBAR);
    const uint32_t mb1 = smem_u32(smem + OFF_MBAR + 8);
    const uint32_t zsa = smem_u32(smem + OFF_ZBUF);
    const uint32_t b0a = smem_u32(smem + OFF_BUF0);
    const uint32_t b1a = smem_u32(smem + OFF_BUF1);

    zbuf[tid] = make_float4(0.0f, 0.0f, 0.0f, 0.0f);
    if (tid == 0) { mbar_init(mb0, 1); mbar_init(mb1, 1); }
    __syncthreads();

    // Prologue: stage row0 into buf0, commit zero-group for row0.
    const int row0 = blockIdx.x;
    if (tid == 0) {
        asm volatile("fence.proxy.async.shared::cta;" ::: "memory");
        mbar_expect_tx(mb0, ROWB);
        const float* src = A + (size_t)row0 * NN;
        bulk_g2s(b0a,         src,        16384, mb0);
        bulk_g2s(b0a + 16384, src + 4096, 16384, mb0);
        float* o0 = out + (size_t)row0 * NN;
        #pragma unroll
        for (int k = 0; k < 8; ++k) bulk_s2g(o0 + k * 1024, zsa, 4096);
        asm volatile("cp.async.bulk.commit_group;" ::: "memory");
    }

    uint32_t phase[2] = {0u, 0u};
    int it = 0;
    for (int row = row0; row < NN; row += NBLK, ++it) {
        const int p = it & 1;
        const int nrow = row + NBLK;
        float* orowf = out + (size_t)row * NN;

        __syncthreads();   // S0: all reads of buf[1-p] (iter it-1) complete

        // Stage next row into the other buffer; commit its zero-group.
        if (nrow < NN && tid == 0) {
            const uint32_t dst = p ? b0a : b1a;
            mbar_expect_tx(p ? mb0 : mb1, ROWB);
            const float* src = A + (size_t)nrow * NN;
            bulk_g2s(dst,         src,        16384, p ? mb0 : mb1);
            bulk_g2s(dst + 16384, src + 4096, 16384, p ? mb0 : mb1);
            float* on = out + (size_t)nrow * NN;
            #pragma unroll
            for (int k = 0; k < 8; ++k) bulk_s2g(on + k * 1024, zsa, 4096);
            asm volatile("cp.async.bulk.commit_group;" ::: "memory");
        }

        // Wait current buffer, then push candidates from smem.
        mbar_wait(p ? mb1 : mb0, phase[p]); phase[p] ^= 1u;
        const float4* bp = reinterpret_cast<const float4*>(smem + (p ? OFF_BUF1 : OFF_BUF0));

        uint64_t* myseg = seg + (warp << 6);
        uint32_t base = 0;
        #pragma unroll
        for (int u = 0; u < 8; ++u) {
            const float4 v = bp[tid + u * NTHREADS];
            const uint32_t eb = (uint32_t)(tid + u * NTHREADS) * 4u;
            unsigned a;
            a = __ballot_sync(0xffffffffu, v.x >= THRESH);
            if (v.x >= THRESH) { uint32_t o = base + __popc(a & ltm); if (o < WCAP) myseg[o] = make_key(__float_as_uint(v.x), eb + 0u); }
            base += (uint32_t)__popc(a);
            a = __ballot_sync(0xffffffffu, v.y >= THRESH);
            if (v.y >= THRESH) { uint32_t o = base + __popc(a & ltm); if (o < WCAP) myseg[o] = make_key(__float_as_uint(v.y), eb + 1u); }
            base += (uint32_t)__popc(a);
            a = __ballot_sync(0xffffffffu, v.z >= THRESH);
            if (v.z >= THRESH) { uint32_t o = base + __popc(a & ltm); if (o < WCAP) myseg[o] = make_key(__float_as_uint(v.z), eb + 2u); }
            base += (uint32_t)__popc(a);
            a = __ballot_sync(0xffffffffu, v.w >= THRESH);
            if (v.w >= THRESH) { uint32_t o = base + __popc(a & ltm); if (o < WCAP) myseg[o] = make_key(__float_as_uint(v.w), eb + 3u); }
            base += (uint32_t)__popc(a);
        }
        if (lane == 0) cnt_s[warp] = base;
        __syncthreads();   // S1

        uint32_t C = 0; bool ok = true;
        uint32_t off[8];
        #pragma unroll
        for (int w = 0; w < 8; ++w) { off[w] = C; const uint32_t cw = cnt_s[w]; C += cw; ok &= (cw <= WCAP); }
        ok = ok && (C >= KSEL) && (C <= DCAP);

        if (ok) {
            #pragma unroll
            for (int s = tid; s < FCAP; s += NTHREADS) {
                const int w = s >> 6, o = s & (WCAP - 1);
                if ((uint32_t)o < cnt_s[w]) dcand[off[w] + o] = seg[s];
            }
            if (tid == 0) {   // retire zeros(row); zeros(nrow) may stay pending
                if (nrow < NN) asm volatile("cp.async.bulk.wait_group 1;" ::: "memory");
                else           asm volatile("cp.async.bulk.wait_group 0;" ::: "memory");
            }
            __syncthreads();  // S2: dcand ready, zeros(row) committed

            for (uint32_t j = tid; j < C; j += NTHREADS) {
                const uint64_t kj = dcand[j];
                uint32_t rr = 0;
                for (uint32_t m = 0; m < C; ++m)
                    rr += (dcand[m] > kj) ? 1u : 0u;       // broadcast LDS
                if (rr < KSEL) {
                    const uint32_t idx = 0xFFFFu ^ (uint32_t)(kj & 0xFFFFu);
                    orowf[idx] = __uint_as_float((uint32_t)(kj >> 16));
                }
            }
            continue;   // next iter's S0 protects reuse
        }

        // ============== Exact fallback (~0.03% of rows), data from smem ==============
        if (tid == 0) {
            if (nrow < NN) asm volatile("cp.async.bulk.wait_group 1;" ::: "memory");
            else           asm volatile("cp.async.bulk.wait_group 0;" ::: "memory");
        }
        if (tid < 4) ctr[tid] = 0;          // fb_count, sh_b, sh_kp, sh_deg
        #pragma unroll
        for (int h = tid; h < 256; h += NTHREADS) hist[h] = 0;
        __syncthreads();

        const float* bf = reinterpret_cast<const float*>(smem + (p ? OFF_BUF1 : OFF_BUF0));
        for (int i = tid; i < NN; i += NTHREADS) {
            const float q = bf[i];
            const uint32_t bits = (q > 0.0f) ? __float_as_uint(q) : 0u;
            hist_add(hist, bits >> 24, bits != 0u, lane);
        }
        __syncthreads();

        {   // suffix scan over 256 byte bins
            const uint32_t v0 = hist[tid];
            uint32_t vv = v0;
            #pragma unroll
            for (int d = 1; d < 32; d <<= 1) {
                uint32_t o = __shfl_down_sync(0xffffffffu, vv, d);
                if (lane + d < 32) vv += o;
            }
            if (lane == 0) wsum[warp] = vv;
            __syncthreads();
            uint32_t hi = 0;
            #pragma unroll
            for (int w = 0; w < 8; ++w) if (w > warp) hi += wsum[w];
            const uint32_t s   = vv + hi;
            const uint32_t nxt = s - v0;
            if (tid == 0 && s < KSEL) ctr[3] = 1;
            if (s >= KSEL && nxt < KSEL) { ctr[1] = (uint32_t)tid; ctr[2] = KSEL - nxt; }
            __syncthreads();
        }
        const uint32_t b   = ctr[1];
        const uint32_t kp  = ctr[2];
        const bool     deg = (ctr[3] != 0);

        for (int i = tid; i < NN; i += NTHREADS) {
            const float q = bf[i];
            const uint32_t bits = (q > 0.0f) ? __float_as_uint(q) : 0u;
            if (deg) {
                if (bits) orowf[i] = q;
            } else if (bits) {
                const uint32_t byte = bits >> 24;
                if (byte > b) orowf[i] = q;
                else if (byte == b) {
                    const uint32_t pp = atomicAdd(&ctr[0], 1u);
                    if (pp < FCAP) seg[pp] = make_key(bits, (uint32_t)i);
                }
            }
        }
        __syncthreads();

        if (!deg) {
            const uint32_t C2 = ctr[0];
            if (C2 <= FCAP) {
                for (uint32_t j = tid; j < C2; j += NTHREADS) {
                    const uint64_t kj = seg[j];
                    uint32_t rr = 0;
                    for (uint32_t mm = 0; mm < C2; ++mm)
                        rr += (seg[mm] > kj) ? 1u : 0u;
                    if (rr < kp) {
                        const uint32_t idx = 0xFFFFu ^ (uint32_t)(kj & 0xFFFFu);
                        orowf[idx] = __uint_as_float((uint32_t)(kj >> 16));
                    }
                }
            } else {
                // duplicate-heavy pathological rows: O(N) exact rank from smem
                for (int i = tid; i < NN; i += NTHREADS) {
                    const float q = bf[i];
                    const uint32_t bits = (q > 0.0f) ? __float_as_uint(q) : 0u;
                    if (bits && (bits >> 24) == b) {
                        const uint64_t kj = make_key(bits, (uint32_t)i);
                        uint32_t rr = 0;
                        for (int j2 = 0; j2 < NN; ++j2) {
                            const float w2 = bf[j2];
                            const uint32_t wb = (w2 > 0.0f) ? __float_as_uint(w2) : 0u;
                            if (wb && (wb >> 24) == b && make_key(wb, (uint32_t)j2) > kj) ++rr;
                        }
                        if (rr < kp) orowf[i] = q;
                    }
                }
            }
        }
    }
}

extern "C" void kernel_launch(void* const* d_in, const int* in_sizes, int n_in,
                              void* d_out, int out_size) {
    const float* A   = (const float*)d_in[0];
    float*       out = (float*)d_out;
    (void)in_sizes; (void)n_in; (void)out_size;   // idx (d_in[1]) unused by the reference
    cudaFuncSetAttribute(topk_mask_kernel, cudaFuncAttributeMaxDynamicSharedMemorySize, SMEM_TOTAL);
    topk_mask_kernel<<<NBLK, NTHREADS, SMEM_TOTAL>>>(A, out);
}

// round 10
// speedup vs baseline: 1.2478x; 1.2478x over previous
#include <cuda_runtime.h>
#include <cstdint>

#define NN        8192
#define KSEL      64
#define NTHREADS  256
#define WCAP      64             // per-warp candidate slots
#define FCAP      (8 * WCAP)     // 512
#define DCAP      256
#define THRESH    2.25f

#define ROWB      (NN * 4)       // 32768 bytes row buffer
#define OFF_BUF   0
#define OFF_ZBUF  32768          // 4096
#define OFF_SEG   36864          // 4096 (512 x u64)
#define OFF_DH    40960          // 2048: dcand (fast) / hist (fallback) union
#define OFF_CNT   43008          // 32: cnt_s[8]
#define OFF_WSUM  43040          // 32
#define OFF_CTR   43072          // 16: fb_count, sh_b, sh_kp, sh_deg
#define OFF_MBAR  43088          // 8
#define SMEM_TOTAL 43104

__device__ __forceinline__ uint64_t make_key(uint32_t bits, uint32_t idx) {
    return ((uint64_t)bits << 16) | (uint64_t)(0xFFFFu ^ idx);
}
__device__ __forceinline__ uint32_t smem_u32(const void* p) {
    return (uint32_t)__cvta_generic_to_shared(p);
}
__device__ __forceinline__ void mbar_init(uint32_t mbar, uint32_t cnt) {
    asm volatile("mbarrier.init.shared.b64 [%0], %1;" :: "r"(mbar), "r"(cnt) : "memory");
}
__device__ __forceinline__ void mbar_expect_tx(uint32_t mbar, uint32_t bytes) {
    asm volatile("mbarrier.arrive.expect_tx.shared.b64 _, [%0], %1;" :: "r"(mbar), "r"(bytes) : "memory");
}
__device__ __forceinline__ void mbar_wait(uint32_t mbar, uint32_t phase) {
    asm volatile(
        "{\n\t.reg .pred P;\n\t"
        "W%=:\n\t"
        "mbarrier.try_wait.parity.acquire.cta.shared::cta.b64 P, [%0], %1, 0x989680;\n\t"
        "@P bra D%=;\n\t"
        "bra W%=;\n\t"
        "D%=:\n\t}"
        :: "r"(mbar), "r"(phase) : "memory");
}
__device__ __forceinline__ void bulk_g2s(uint32_t dst, const void* src, uint32_t bytes, uint32_t mbar) {
    asm volatile("cp.async.bulk.shared::cluster.global.mbarrier::complete_tx::bytes [%0], [%1], %2, [%3];"
                 :: "r"(dst), "l"(src), "r"(bytes), "r"(mbar) : "memory");
}
__device__ __forceinline__ void bulk_s2g(void* dst, uint32_t src, uint32_t bytes) {
    asm volatile("cp.async.bulk.global.shared::cta.bulk_group [%0], [%1], %2;"
                 :: "l"(dst), "r"(src), "r"(bytes) : "memory");
}

// Warp-aggregated histogram add (fallback only).
__device__ __forceinline__ void hist_add(uint32_t* hist, uint32_t bin, bool pred, int lane) {
    unsigned act = __ballot_sync(0xffffffffu, pred);
    if (pred) {
        unsigned same   = __match_any_sync(act, bin);
        int      leader = __ffs(same) - 1;
        if (lane == leader) atomicAdd(&hist[bin], (uint32_t)__popc(same));
    }
}

extern __shared__ char smem[];

__global__ __launch_bounds__(NTHREADS)
void topk_mask_kernel(const float* __restrict__ A, float* __restrict__ out)
{
    const int tid  = threadIdx.x;
    const int lane = tid & 31;
    const int warp = tid >> 5;
    const unsigned ltm = (1u << lane) - 1u;
    const size_t row = blockIdx.x;

    float4*   zbuf  = reinterpret_cast<float4*>(smem + OFF_ZBUF);
    uint64_t* seg   = reinterpret_cast<uint64_t*>(smem + OFF_SEG);
    uint64_t* dcand = reinterpret_cast<uint64_t*>(smem + OFF_DH);
    uint32_t* hist  = reinterpret_cast<uint32_t*>(smem + OFF_DH);
    uint32_t* cnt_s = reinterpret_cast<uint32_t*>(smem + OFF_CNT);
    uint32_t* wsum  = reinterpret_cast<uint32_t*>(smem + OFF_WSUM);
    uint32_t* ctr   = reinterpret_cast<uint32_t*>(smem + OFF_CTR);  // fb,b,kp,deg
    const uint32_t mb  = smem_u32(smem + OFF_MBAR);
    const uint32_t zsa = smem_u32(smem + OFF_ZBUF);
    const uint32_t bfa = smem_u32(smem + OFF_BUF);

    zbuf[tid] = make_float4(0.0f, 0.0f, 0.0f, 0.0f);
    if (tid == 0) mbar_init(mb, 1);
    __syncthreads();

    float* orowf = out + row * (size_t)NN;

    // Kick off the whole row's traffic: async read of A-row into smem, async
    // zero-fill of the output row. Warps then sleep on the mbarrier while the
    // TMA engines stream; cross-block interleaving (4 blocks/SM) keeps DRAM busy.
    if (tid == 0) {
        asm volatile("fence.proxy.async.shared::cta;" ::: "memory");
        mbar_expect_tx(mb, ROWB);
        const float* src = A + row * (size_t)NN;
        bulk_g2s(bfa,         src,        16384, mb);
        bulk_g2s(bfa + 16384, src + 4096, 16384, mb);
        #pragma unroll
        for (int k = 0; k < 8; ++k) bulk_s2g(orowf + k * 1024, zsa, 4096);
        asm volatile("cp.async.bulk.commit_group;" ::: "memory");
    }
    mbar_wait(mb, 0);

    // ---- Sweep from shared memory: ballot-compacted candidate push ----
    const float4* bp = reinterpret_cast<const float4*>(smem + OFF_BUF);
    uint64_t* myseg = seg + (warp << 6);
    uint32_t base = 0;
    #pragma unroll
    for (int u = 0; u < 8; ++u) {
        const float4 v = bp[tid + u * NTHREADS];
        const uint32_t eb = (uint32_t)(tid + u * NTHREADS) * 4u;
        unsigned a;
        a = __ballot_sync(0xffffffffu, v.x >= THRESH);
        if (v.x >= THRESH) { uint32_t o = base + __popc(a & ltm); if (o < WCAP) myseg[o] = make_key(__float_as_uint(v.x), eb + 0u); }
        base += (uint32_t)__popc(a);
        a = __ballot_sync(0xffffffffu, v.y >= THRESH);
        if (v.y >= THRESH) { uint32_t o = base + __popc(a & ltm); if (o < WCAP) myseg[o] = make_key(__float_as_uint(v.y), eb + 1u); }
        base += (uint32_t)__popc(a);
        a = __ballot_sync(0xffffffffu, v.z >= THRESH);
        if (v.z >= THRESH) { uint32_t o = base + __popc(a & ltm); if (o < WCAP) myseg[o] = make_key(__float_as_uint(v.z), eb + 2u); }
        base += (uint32_t)__popc(a);
        a = __ballot_sync(0xffffffffu, v.w >= THRESH);
        if (v.w >= THRESH) { uint32_t o = base + __popc(a & ltm); if (o < WCAP) myseg[o] = make_key(__float_as_uint(v.w), eb + 3u); }
        base += (uint32_t)__popc(a);
    }
    if (lane == 0) cnt_s[warp] = base;
    __syncthreads();

    uint32_t C = 0; bool ok = true;
    uint32_t off[8];
    #pragma unroll
    for (int w = 0; w < 8; ++w) { off[w] = C; const uint32_t cw = cnt_s[w]; C += cw; ok &= (cw <= WCAP); }
    ok = ok && (C >= KSEL) && (C <= DCAP);

    if (ok) {
        // compact into dense dcand[0..C)
        #pragma unroll
        for (int s = tid; s < FCAP; s += NTHREADS) {
            const int w = s >> 6, o = s & (WCAP - 1);
            if ((uint32_t)o < cnt_s[w]) dcand[off[w] + o] = seg[s];
        }
        if (tid == 0) asm volatile("cp.async.bulk.wait_group 0;" ::: "memory");
        __syncthreads();   // dcand ready, zeros committed

        // exact rank (value desc, index asc); scatter the KSEL winners
        for (uint32_t j = tid; j < C; j += NTHREADS) {
            const uint64_t kj = dcand[j];
            uint32_t rr = 0;
            for (uint32_t m = 0; m < C; ++m)
                rr += (dcand[m] > kj) ? 1u : 0u;       // broadcast LDS
            if (rr < KSEL) {
                const uint32_t idx = 0xFFFFu ^ (uint32_t)(kj & 0xFFFFu);
                orowf[idx] = __uint_as_float((uint32_t)(kj >> 16));
            }
        }
        return;
    }

    // ============== Exact fallback (~0.02% of rows), data from smem ==============
    if (tid == 0) asm volatile("cp.async.bulk.wait_group 0;" ::: "memory");
    if (tid < 4) ctr[tid] = 0;              // fb_count, sh_b, sh_kp, sh_deg
    #pragma unroll
    for (int h = tid; h < 256; h += NTHREADS) hist[h] = 0;
    __syncthreads();

    const float* bf = reinterpret_cast<const float*>(smem + OFF_BUF);
    for (int i = tid; i < NN; i += NTHREADS) {
        const float q = bf[i];
        const uint32_t bits = (q > 0.0f) ? __float_as_uint(q) : 0u;
        hist_add(hist, bits >> 24, bits != 0u, lane);
    }
    __syncthreads();

    {   // suffix scan over 256 byte bins
        const uint32_t v0 = hist[tid];
        uint32_t vv = v0;
        #pragma unroll
        for (int d = 1; d < 32; d <<= 1) {
            uint32_t o = __shfl_down_sync(0xffffffffu, vv, d);
            if (lane + d < 32) vv += o;
        }
        if (lane == 0) wsum[warp] = vv;
        __syncthreads();
        uint32_t hi = 0;
        #pragma unroll
        for (int w = 0; w < 8; ++w) if (w > warp) hi += wsum[w];
        const uint32_t s   = vv + hi;
        const uint32_t nxt = s - v0;
        if (tid == 0 && s < KSEL) ctr[3] = 1;
        if (s >= KSEL && nxt < KSEL) { ctr[1] = (uint32_t)tid; ctr[2] = KSEL - nxt; }
        __syncthreads();
    }
    const uint32_t b   = ctr[1];
    const uint32_t kp  = ctr[2];
    const bool     deg = (ctr[3] != 0);

    for (int i = tid; i < NN; i += NTHREADS) {
        const float q = bf[i];
        const uint32_t bits = (q > 0.0f) ? __float_as_uint(q) : 0u;
        if (deg) {
            if (bits) orowf[i] = q;                    // <K positives: keep all
        } else if (bits) {
            const uint32_t byte = bits >> 24;
            if (byte > b) orowf[i] = q;
            else if (byte == b) {
                const uint32_t pp = atomicAdd(&ctr[0], 1u);
                if (pp < FCAP) seg[pp] = make_key(bits, (uint32_t)i);
            }
        }
    }
    __syncthreads();

    if (!deg) {
        const uint32_t C2 = ctr[0];
        if (C2 <= FCAP) {
            for (uint32_t j = tid; j < C2; j += NTHREADS) {
                const uint64_t kj = seg[j];
                uint32_t rr = 0;
                for (uint32_t mm = 0; mm < C2; ++mm)
                    rr += (seg[mm] > kj) ? 1u : 0u;
                if (rr < kp) {
                    const uint32_t idx = 0xFFFFu ^ (uint32_t)(kj & 0xFFFFu);
                    orowf[idx] = __uint_as_float((uint32_t)(kj >> 16));
                }
            }
        } else {
            // duplicate-heavy pathological rows: O(N) exact rank from smem
            for (int i = tid; i < NN; i += NTHREADS) {
                const float q = bf[i];
                const uint32_t bits = (q > 0.0f) ? __float_as_uint(q) : 0u;
                if (bits && (bits >> 24) == b) {
                    const uint64_t kj = make_key(bits, (uint32_t)i);
                    uint32_t rr = 0;
                    for (int j2 = 0; j2 < NN; ++j2) {
                        const float w2 = bf[j2];
                        const uint32_t wb = (w2 > 0.0f) ? __float_as_uint(w2) : 0u;
                        if (wb && (wb >> 24) == b && make_key(wb, (uint32_t)j2) > kj) ++rr;
                    }
                    if (rr < kp) orowf[i] = q;
                }
            }
        }
    }
}

extern "C" void kernel_launch(void* const* d_in, const int* in_sizes, int n_in,
                              void* d_out, int out_size) {
    const float* A   = (const float*)d_in[0];
    float*       out = (float*)d_out;
    (void)in_sizes; (void)n_in; (void)out_size;   // idx (d_in[1]) unused by the reference
    cudaFuncSetAttribute(topk_mask_kernel, cudaFuncAttributeMaxDynamicSharedMemorySize, SMEM_TOTAL);
    topk_mask_kernel<<<NN, NTHREADS, SMEM_TOTAL>>>(A, out);
}